// round 3
// baseline (speedup 1.0000x reference)
#include <cuda_runtime.h>

#define AA   64
#define TT   512
#define DD   256
#define HH   4
#define HDIM 64
#define AT   (AA*TT)

// Scratch (allocation-free): 4 x 33.5MB
__device__ float g_q[AT*DD];
__device__ float g_k[AT*DD];
__device__ float g_v[AT*DD];
__device__ float g_ctx[AT*DD];

// ---------------------------------------------------------------------------
// GEMM: Y[M,256] = X[M,256] @ W[256,256]^T + bias   (M = 32768 fixed)
// BM=BN=64, BK=32, 256 threads, 4x4 per thread.
// ---------------------------------------------------------------------------
__global__ __launch_bounds__(256) void gemm_xwt(
    const float* __restrict__ X, const float* __restrict__ W,
    const float* __restrict__ bias, float* __restrict__ Y)
{
    __shared__ float As[32][68];   // [k][m], padded stride 68 (16B-aligned rows)
    __shared__ float Bs[32][68];   // [k][n]

    const int m0  = blockIdx.x * 64;
    const int n0  = blockIdx.y * 64;
    const int tid = threadIdx.x;
    const int tx  = tid & 15;      // n-group
    const int ty  = tid >> 4;      // m-group

    const int r  = tid >> 3;       // 0..31 (row within 32-row pass)
    const int c4 = (tid & 7) << 2; // 0..28 (k quad)

    float acc[4][4] = {};

    for (int k0 = 0; k0 < 256; k0 += 32) {
        #pragma unroll
        for (int rr = 0; rr < 64; rr += 32) {
            float4 xv = *(const float4*)&X[(size_t)(m0 + r + rr) * DD + k0 + c4];
            As[c4+0][r+rr] = xv.x; As[c4+1][r+rr] = xv.y;
            As[c4+2][r+rr] = xv.z; As[c4+3][r+rr] = xv.w;
            float4 wv = *(const float4*)&W[(size_t)(n0 + r + rr) * DD + k0 + c4];
            Bs[c4+0][r+rr] = wv.x; Bs[c4+1][r+rr] = wv.y;
            Bs[c4+2][r+rr] = wv.z; Bs[c4+3][r+rr] = wv.w;
        }
        __syncthreads();

        #pragma unroll
        for (int k = 0; k < 32; k++) {
            float4 a = *(const float4*)&As[k][ty << 2];
            float4 b = *(const float4*)&Bs[k][tx << 2];
            acc[0][0] += a.x*b.x; acc[0][1] += a.x*b.y; acc[0][2] += a.x*b.z; acc[0][3] += a.x*b.w;
            acc[1][0] += a.y*b.x; acc[1][1] += a.y*b.y; acc[1][2] += a.y*b.z; acc[1][3] += a.y*b.w;
            acc[2][0] += a.z*b.x; acc[2][1] += a.z*b.y; acc[2][2] += a.z*b.z; acc[2][3] += a.z*b.w;
            acc[3][0] += a.w*b.x; acc[3][1] += a.w*b.y; acc[3][2] += a.w*b.z; acc[3][3] += a.w*b.w;
        }
        __syncthreads();
    }

    #pragma unroll
    for (int i = 0; i < 4; i++) {
        const int m = m0 + (ty << 2) + i;
        #pragma unroll
        for (int j = 0; j < 4; j++) {
            const int n = n0 + (tx << 2) + j;
            Y[(size_t)m * DD + n] = acc[i][j] + bias[n];
        }
    }
}

// ---------------------------------------------------------------------------
// Banded sparse attention with online softmax.
// Block: 32 queries of one (a,h). 256 threads = 8 warps; warp w owns queries
// w*4 .. w*4+3. Keys streamed in chunks of 32 (band read in-kernel from tw).
// Scores: key-parallel (lane = key, K^T in smem).  AV: d-parallel (lane = 2 dims).
// ---------------------------------------------------------------------------
__global__ __launch_bounds__(256) void attn_banded(
    const float* __restrict__ pos,
    const int* __restrict__ p_md, const int* __restrict__ p_tw)
{
    __shared__ float Qs[32][HDIM];   // scaled Q
    __shared__ float Kt[HDIM][33];   // K chunk transposed [d][key]
    __shared__ float Vs[32][HDIM];   // V chunk [key][d]
    __shared__ float Ps[32][32];     // probs per chunk

    const int a    = blockIdx.z;
    const int h    = blockIdx.y;
    const int q0   = blockIdx.x * 32;
    const int tid  = threadIdx.x;
    const int w    = tid >> 5;
    const int lane = tid & 31;

    const int   tw  = *p_tw;
    const float mdf = (float)(*p_md);
    const float md2 = mdf * mdf;

    // Load + pre-scale Q tile (scale = 1/sqrt(64) = 0.125)
    {
        const float* qbase = g_q + (size_t)(a*TT + q0) * DD + h*HDIM;
        #pragma unroll
        for (int i = tid; i < 32*16; i += 256) {
            const int r  = i >> 4;
            const int c4 = (i & 15) << 2;
            float4 v = *(const float4*)&qbase[(size_t)r * DD + c4];
            v.x *= 0.125f; v.y *= 0.125f; v.z *= 0.125f; v.w *= 0.125f;
            *(float4*)&Qs[r][c4] = v;
        }
    }

    // Per-warp query state (replicated across lanes)
    float pqx[4], pqy[4];
    #pragma unroll
    for (int i = 0; i < 4; i++) {
        const int qg = q0 + w*4 + i;
        pqx[i] = pos[(size_t)(a*TT + qg)*2 + 0];
        pqy[i] = pos[(size_t)(a*TT + qg)*2 + 1];
    }
    float mrow[4] = {-1e30f, -1e30f, -1e30f, -1e30f};
    float lrow[4] = {0.f, 0.f, 0.f, 0.f};
    float oacc[4][2] = {};

    int jlo = q0 - tw;       if (jlo < 0)      jlo = 0;
    int jhi = q0 + 31 + tw;  if (jhi > TT - 1) jhi = TT - 1;

    __syncthreads();

    for (int c0 = jlo; c0 <= jhi; c0 += 32) {
        const int cn = min(32, jhi - c0 + 1);

        // Stage K chunk (transposed) and V chunk (zero-fill tail rows of V)
        {
            const float* kbase = g_k + (size_t)(a*TT + c0) * DD + h*HDIM;
            const float* vbase = g_v + (size_t)(a*TT + c0) * DD + h*HDIM;
            #pragma unroll
            for (int i = tid; i < 32*16; i += 256) {
                const int r  = i >> 4;
                const int c4 = (i & 15) << 2;
                if (r < cn) {
                    float4 kv = *(const float4*)&kbase[(size_t)r * DD + c4];
                    Kt[c4+0][r] = kv.x; Kt[c4+1][r] = kv.y;
                    Kt[c4+2][r] = kv.z; Kt[c4+3][r] = kv.w;
                    *(float4*)&Vs[r][c4] = *(const float4*)&vbase[(size_t)r * DD + c4];
                } else {
                    const float4 z = {0.f, 0.f, 0.f, 0.f};
                    *(float4*)&Vs[r][c4] = z;
                }
            }
        }
        __syncthreads();

        // ---- scores (lane = key within chunk) ----
        const int  jg   = c0 + lane;
        const bool lval = (lane < cn);
        float pkx = 0.f, pky = 0.f;
        if (lval) {
            pkx = pos[(size_t)(a*TT + jg)*2 + 0];
            pky = pos[(size_t)(a*TT + jg)*2 + 1];
        }

        float sf[4];
        #pragma unroll
        for (int i = 0; i < 4; i++) {
            const int ql = w*4 + i;
            float s0 = 0.f, s1 = 0.f, s2 = 0.f, s3 = 0.f;
            #pragma unroll
            for (int d4 = 0; d4 < 16; d4++) {
                const float4 qv = *(const float4*)&Qs[ql][d4 << 2];
                s0 += qv.x * Kt[(d4<<2)+0][lane];
                s1 += qv.y * Kt[(d4<<2)+1][lane];
                s2 += qv.z * Kt[(d4<<2)+2][lane];
                s3 += qv.w * Kt[(d4<<2)+3][lane];
            }
            float s = (s0 + s1) + (s2 + s3);

            // mask: time band + spatial distance
            const int qg = q0 + ql;
            int dt = qg - jg; dt = dt < 0 ? -dt : dt;
            const float dx = pqx[i] - pkx;
            const float dy = pqy[i] - pky;
            const bool ok = lval && (dt <= tw) && (dx*dx + dy*dy <= md2);
            if (!ok) s = -1e30f;

            float cm = s;
            #pragma unroll
            for (int off = 16; off; off >>= 1)
                cm = fmaxf(cm, __shfl_xor_sync(0xffffffffu, cm, off));
            const float mi = fmaxf(mrow[i], cm);

            float p = ok ? __expf(s - mi) : 0.f;
            float cs = p;
            #pragma unroll
            for (int off = 16; off; off >>= 1)
                cs += __shfl_xor_sync(0xffffffffu, cs, off);

            sf[i]   = __expf(mrow[i] - mi);
            lrow[i] = lrow[i] * sf[i] + cs;
            mrow[i] = mi;
            Ps[ql][lane] = p;
        }
        __syncwarp();

        // ---- AV (lane = dim pair) ----
        #pragma unroll
        for (int i = 0; i < 4; i++) {
            const int ql = w*4 + i;
            float o0 = oacc[i][0] * sf[i];
            float o1 = oacc[i][1] * sf[i];
            #pragma unroll
            for (int j = 0; j < 32; j++) {
                const float  p = Ps[ql][j];
                const float2 v = *(const float2*)&Vs[j][lane << 1];
                o0 += p * v.x;
                o1 += p * v.y;
            }
            oacc[i][0] = o0; oacc[i][1] = o1;
        }
        __syncthreads();
    }

    // normalize + write context
    #pragma unroll
    for (int i = 0; i < 4; i++) {
        const int   qg  = q0 + w*4 + i;
        const float inv = 1.f / lrow[i];
        float2 r;
        r.x = oacc[i][0] * inv;
        r.y = oacc[i][1] * inv;
        *(float2*)&g_ctx[(size_t)(a*TT + qg) * DD + h*HDIM + (lane << 1)] = r;
    }
}

// ---------------------------------------------------------------------------
// Launch
// ---------------------------------------------------------------------------
extern "C" void kernel_launch(void* const* d_in, const int* in_sizes, int n_in,
                              void* d_out, int out_size)
{
    const float* feat = (const float*)d_in[0];
    const float* posn = (const float*)d_in[1];
    const float* Wq   = (const float*)d_in[2];
    const float* bq   = (const float*)d_in[3];
    const float* Wk   = (const float*)d_in[4];
    const float* bk   = (const float*)d_in[5];
    const float* Wv   = (const float*)d_in[6];
    const float* bv   = (const float*)d_in[7];
    const float* Wo   = (const float*)d_in[8];
    const float* bo   = (const float*)d_in[9];
    const int*   pmd  = (const int*)d_in[10];
    const int*   ptw  = (const int*)d_in[11];

    void *pq, *pk, *pv, *pctx;
    cudaGetSymbolAddress(&pq,   g_q);
    cudaGetSymbolAddress(&pk,   g_k);
    cudaGetSymbolAddress(&pv,   g_v);
    cudaGetSymbolAddress(&pctx, g_ctx);

    const dim3 gg(AT/64, DD/64, 1);   // 512 x 4
    gemm_xwt<<<gg, 256>>>(feat, Wq, bq, (float*)pq);
    gemm_xwt<<<gg, 256>>>(feat, Wk, bk, (float*)pk);
    gemm_xwt<<<gg, 256>>>(feat, Wv, bv, (float*)pv);

    attn_banded<<<dim3(TT/32, HH, AA), 256>>>(posn, pmd, ptw);

    gemm_xwt<<<gg, 256>>>((const float*)pctx, Wo, bo, (float*)d_out);
}

// round 4
// speedup vs baseline: 1.4949x; 1.4949x over previous
#include <cuda_runtime.h>

#define AA   64
#define TT   512
#define DD   256
#define HH   4
#define HDIM 64
#define AT   (AA*TT)

typedef unsigned long long ull;

// Scratch (allocation-free)
__device__ float g_q[AT*DD];
__device__ float g_k[AT*DD];
__device__ float g_v[AT*DD];
__device__ float g_ctx[AT*DD];

// ---------------------------------------------------------------------------
// f32x2 packed-math helpers (sm_103a FFMA2 path — ptxas never auto-emits)
// ---------------------------------------------------------------------------
__device__ __forceinline__ ull dup2(float x) {
    ull r;
    asm("mov.b64 %0, {%1, %1};" : "=l"(r) : "r"(__float_as_uint(x)));
    return r;
}
__device__ __forceinline__ void fma2(ull &d, ull a, ull b) {
    asm("fma.rn.f32x2 %0, %1, %2, %0;" : "+l"(d) : "l"(a), "l"(b));
}
__device__ __forceinline__ ull mul2(ull a, ull b) {
    ull r;
    asm("mul.rn.f32x2 %0, %1, %2;" : "=l"(r) : "l"(a), "l"(b));
    return r;
}
__device__ __forceinline__ float2 unpack2(ull v) {
    float2 f;
    asm("mov.b64 {%0, %1}, %2;" : "=f"(f.x), "=f"(f.y) : "l"(v));
    return f;
}

// ---------------------------------------------------------------------------
// GEMM body: Y[128x128 tile] = X @ W^T + bias, K=256.
// BM=BN=128, BK=16, 256 threads, 8x8 per thread via FFMA2 (pairs along n).
// ---------------------------------------------------------------------------
__device__ __forceinline__ void gemm_body(
    const float* __restrict__ X, const float* __restrict__ W,
    const float* __restrict__ bias, float* __restrict__ Y,
    int m0, int n0)
{
    __shared__ float As[16][132];   // [k][m]
    __shared__ float Bs[16][132];   // [k][n]

    const int tid = threadIdx.x;
    const int tx  = tid & 15;        // n-frag
    const int ty  = tid >> 4;        // m-frag
    const int lr  = tid >> 2;        // 0..63 load row
    const int lc  = (tid & 3) << 2;  // 0..12 load k-quad

    ull acc[8][4];
    #pragma unroll
    for (int i = 0; i < 8; i++)
        #pragma unroll
        for (int j = 0; j < 4; j++) acc[i][j] = 0ull;

    for (int k0 = 0; k0 < 256; k0 += 16) {
        float4 x0 = *(const float4*)&X[(size_t)(m0 + lr)      * DD + k0 + lc];
        float4 x1 = *(const float4*)&X[(size_t)(m0 + 64 + lr) * DD + k0 + lc];
        float4 w0 = *(const float4*)&W[(size_t)(n0 + lr)      * DD + k0 + lc];
        float4 w1 = *(const float4*)&W[(size_t)(n0 + 64 + lr) * DD + k0 + lc];
        __syncthreads();   // prior-iter reads of As/Bs complete
        As[lc+0][lr] = x0.x; As[lc+1][lr] = x0.y; As[lc+2][lr] = x0.z; As[lc+3][lr] = x0.w;
        As[lc+0][64+lr] = x1.x; As[lc+1][64+lr] = x1.y; As[lc+2][64+lr] = x1.z; As[lc+3][64+lr] = x1.w;
        Bs[lc+0][lr] = w0.x; Bs[lc+1][lr] = w0.y; Bs[lc+2][lr] = w0.z; Bs[lc+3][lr] = w0.w;
        Bs[lc+0][64+lr] = w1.x; Bs[lc+1][64+lr] = w1.y; Bs[lc+2][64+lr] = w1.z; Bs[lc+3][64+lr] = w1.w;
        __syncthreads();

        #pragma unroll
        for (int k = 0; k < 16; k++) {
            float4 a0 = *(const float4*)&As[k][ty << 2];
            float4 a1 = *(const float4*)&As[k][64 + (ty << 2)];
            ulonglong2 bb0 = *(const ulonglong2*)&Bs[k][tx << 2];
            ulonglong2 bb1 = *(const ulonglong2*)&Bs[k][64 + (tx << 2)];
            ull am[8] = { dup2(a0.x), dup2(a0.y), dup2(a0.z), dup2(a0.w),
                          dup2(a1.x), dup2(a1.y), dup2(a1.z), dup2(a1.w) };
            #pragma unroll
            for (int mi = 0; mi < 8; mi++) {
                fma2(acc[mi][0], am[mi], bb0.x);
                fma2(acc[mi][1], am[mi], bb0.y);
                fma2(acc[mi][2], am[mi], bb1.x);
                fma2(acc[mi][3], am[mi], bb1.y);
            }
        }
    }

    float4 bv0 = *(const float4*)&bias[n0 + (tx << 2)];
    float4 bv1 = *(const float4*)&bias[n0 + 64 + (tx << 2)];
    #pragma unroll
    for (int mi = 0; mi < 8; mi++) {
        const int m = m0 + ((mi < 4) ? ((ty << 2) + mi) : (64 + (ty << 2) + mi - 4));
        float2 p0 = unpack2(acc[mi][0]);
        float2 p1 = unpack2(acc[mi][1]);
        float4 r0 = { p0.x + bv0.x, p0.y + bv0.y, p1.x + bv0.z, p1.y + bv0.w };
        *(float4*)&Y[(size_t)m * DD + n0 + (tx << 2)] = r0;
        float2 p2 = unpack2(acc[mi][2]);
        float2 p3 = unpack2(acc[mi][3]);
        float4 r1 = { p2.x + bv1.x, p2.y + bv1.y, p3.x + bv1.z, p3.y + bv1.w };
        *(float4*)&Y[(size_t)m * DD + n0 + 64 + (tx << 2)] = r1;
    }
}

// Fused Q/K/V projection: blockIdx.z selects the weight/bias/output set.
__global__ __launch_bounds__(256, 2) void gemm_qkv(
    const float* __restrict__ X,
    const float* __restrict__ Wq, const float* __restrict__ Wk, const float* __restrict__ Wv,
    const float* __restrict__ bq, const float* __restrict__ bk, const float* __restrict__ bv,
    float* __restrict__ Yq, float* __restrict__ Yk, float* __restrict__ Yv)
{
    const int z = blockIdx.z;
    const float* W = (z == 0) ? Wq : (z == 1) ? Wk : Wv;
    const float* b = (z == 0) ? bq : (z == 1) ? bk : bv;
    float*       Y = (z == 0) ? Yq : (z == 1) ? Yk : Yv;
    gemm_body(X, W, b, Y, blockIdx.x * 128, blockIdx.y * 128);
}

__global__ __launch_bounds__(256, 2) void gemm_single(
    const float* __restrict__ X, const float* __restrict__ W,
    const float* __restrict__ bias, float* __restrict__ Y)
{
    gemm_body(X, W, bias, Y, blockIdx.x * 128, blockIdx.y * 128);
}

// ---------------------------------------------------------------------------
// Banded sparse attention, online softmax.
// Block: 32 queries of one (a,h); 8 warps, warp w owns queries w*4..w*4+3.
// Scores: lane = key; K row-major float4 loads shared across the 4 queries,
//         f32x2 packed dot-product accumulation.
// AV:     lane = dim-pair; p broadcast via warp shuffle (no smem Ps).
// ---------------------------------------------------------------------------
__global__ __launch_bounds__(256, 2) void attn_banded(
    const float* __restrict__ pos,
    const int* __restrict__ p_md, const int* __restrict__ p_tw)
{
    __shared__ float Qs[32][68];   // scaled Q  [q][d]
    __shared__ float Ks[32][68];   // K chunk   [key][d]
    __shared__ float Vs[32][68];   // V chunk   [key][d]

    const int a    = blockIdx.z;
    const int h    = blockIdx.y;
    const int q0   = blockIdx.x * 32;
    const int tid  = threadIdx.x;
    const int w    = tid >> 5;
    const int lane = tid & 31;
    const int w4   = w << 2;

    const int   tw  = *p_tw;
    const float mdf = (float)(*p_md);
    const float md2 = mdf * mdf;

    // Stage + pre-scale Q (scale = 1/sqrt(64))
    {
        const float* qbase = g_q + (size_t)(a*TT + q0) * DD + h*HDIM;
        #pragma unroll
        for (int i = tid; i < 32*16; i += 256) {
            const int r  = i >> 4;
            const int c4 = (i & 15) << 2;
            float4 v = *(const float4*)&qbase[(size_t)r * DD + c4];
            v.x *= 0.125f; v.y *= 0.125f; v.z *= 0.125f; v.w *= 0.125f;
            *(float4*)&Qs[r][c4] = v;
        }
    }

    float pqx[4], pqy[4];
    #pragma unroll
    for (int i = 0; i < 4; i++) {
        const int qg = q0 + w4 + i;
        pqx[i] = pos[(size_t)(a*TT + qg)*2 + 0];
        pqy[i] = pos[(size_t)(a*TT + qg)*2 + 1];
    }
    float mrow[4] = {-1e30f, -1e30f, -1e30f, -1e30f};
    float lrow[4] = {0.f, 0.f, 0.f, 0.f};
    ull   o2[4]   = {0ull, 0ull, 0ull, 0ull};   // (dim lane*2, lane*2+1)

    int jlo = q0 - tw;       if (jlo < 0)      jlo = 0;
    int jhi = q0 + 31 + tw;  if (jhi > TT - 1) jhi = TT - 1;

    for (int c0 = jlo; c0 <= jhi; c0 += 32) {
        const int cn = min(32, jhi - c0 + 1);

        __syncthreads();   // prior chunk's reads of Ks/Vs done (also covers Qs stage)
        {
            const float* kbase = g_k + (size_t)(a*TT + c0) * DD + h*HDIM;
            const float* vbase = g_v + (size_t)(a*TT + c0) * DD + h*HDIM;
            #pragma unroll
            for (int i = tid; i < 32*16; i += 256) {
                const int r  = i >> 4;
                const int c4 = (i & 15) << 2;
                if (r < cn) {
                    *(float4*)&Ks[r][c4] = *(const float4*)&kbase[(size_t)r * DD + c4];
                    *(float4*)&Vs[r][c4] = *(const float4*)&vbase[(size_t)r * DD + c4];
                } else {
                    const float4 z = {0.f, 0.f, 0.f, 0.f};
                    *(float4*)&Vs[r][c4] = z;   // V tail must be 0 (K tail is masked)
                }
            }
        }
        __syncthreads();

        // ---- scores (lane = key in chunk) ----
        const int  jg   = c0 + lane;
        const bool lval = (lane < cn);
        float pkx = 0.f, pky = 0.f;
        if (lval) {
            pkx = pos[(size_t)(a*TT + jg)*2 + 0];
            pky = pos[(size_t)(a*TT + jg)*2 + 1];
        }

        ull s2[4] = {0ull, 0ull, 0ull, 0ull};
        #pragma unroll
        for (int d4 = 0; d4 < 16; d4++) {
            ulonglong2 kk = *(const ulonglong2*)&Ks[lane][d4 << 2];
            #pragma unroll
            for (int i = 0; i < 4; i++) {
                ulonglong2 qq = *(const ulonglong2*)&Qs[w4 + i][d4 << 2];  // broadcast
                fma2(s2[i], qq.x, kk.x);
                fma2(s2[i], qq.y, kk.y);
            }
        }

        float p_reg[4], sf[4];
        #pragma unroll
        for (int i = 0; i < 4; i++) {
            float2 sv = unpack2(s2[i]);
            float  s  = sv.x + sv.y;

            const int qg = q0 + w4 + i;
            int dt = qg - jg; dt = dt < 0 ? -dt : dt;
            const float dx = pqx[i] - pkx;
            const float dy = pqy[i] - pky;
            const bool ok = lval && (dt <= tw) && (dx*dx + dy*dy <= md2);
            if (!ok) s = -1e30f;

            float cm = s;
            #pragma unroll
            for (int off = 16; off; off >>= 1)
                cm = fmaxf(cm, __shfl_xor_sync(0xffffffffu, cm, off));
            const float mi = fmaxf(mrow[i], cm);

            float p = ok ? __expf(s - mi) : 0.f;
            float cs = p;
            #pragma unroll
            for (int off = 16; off; off >>= 1)
                cs += __shfl_xor_sync(0xffffffffu, cs, off);

            sf[i]    = __expf(mrow[i] - mi);
            lrow[i]  = lrow[i] * sf[i] + cs;
            mrow[i]  = mi;
            p_reg[i] = p;
        }

        // ---- AV (lane = dim pair); p via shuffle, no smem staging ----
        #pragma unroll
        for (int i = 0; i < 4; i++)
            o2[i] = mul2(o2[i], dup2(sf[i]));

        #pragma unroll
        for (int j = 0; j < 32; j++) {
            ull vv = *(const ull*)&Vs[j][lane << 1];
            #pragma unroll
            for (int i = 0; i < 4; i++) {
                float pj = __shfl_sync(0xffffffffu, p_reg[i], j);
                fma2(o2[i], dup2(pj), vv);
            }
        }
    }

    // normalize + write context
    #pragma unroll
    for (int i = 0; i < 4; i++) {
        const int   qg  = q0 + w4 + i;
        const float inv = 1.f / lrow[i];
        float2 ov = unpack2(o2[i]);
        float2 r;
        r.x = ov.x * inv;
        r.y = ov.y * inv;
        *(float2*)&g_ctx[(size_t)(a*TT + qg) * DD + h*HDIM + (lane << 1)] = r;
    }
}

// ---------------------------------------------------------------------------
// Launch
// ---------------------------------------------------------------------------
extern "C" void kernel_launch(void* const* d_in, const int* in_sizes, int n_in,
                              void* d_out, int out_size)
{
    const float* feat = (const float*)d_in[0];
    const float* posn = (const float*)d_in[1];
    const float* Wq   = (const float*)d_in[2];
    const float* bq   = (const float*)d_in[3];
    const float* Wk   = (const float*)d_in[4];
    const float* bk   = (const float*)d_in[5];
    const float* Wv   = (const float*)d_in[6];
    const float* bv   = (const float*)d_in[7];
    const float* Wo   = (const float*)d_in[8];
    const float* bo   = (const float*)d_in[9];
    const int*   pmd  = (const int*)d_in[10];
    const int*   ptw  = (const int*)d_in[11];

    void *pq, *pk, *pv, *pctx;
    cudaGetSymbolAddress(&pq,   g_q);
    cudaGetSymbolAddress(&pk,   g_k);
    cudaGetSymbolAddress(&pv,   g_v);
    cudaGetSymbolAddress(&pctx, g_ctx);

    gemm_qkv<<<dim3(AT/128, DD/128, 3), 256>>>(
        feat, Wq, Wk, Wv, bq, bk, bv, (float*)pq, (float*)pk, (float*)pv);

    attn_banded<<<dim3(TT/32, HH, AA), 256>>>(posn, pmd, ptw);

    gemm_single<<<dim3(AT/128, DD/128, 1), 256>>>(
        (const float*)pctx, Wo, bo, (float*)d_out);
}